// round 15
// baseline (speedup 1.0000x reference)
#include <cuda_runtime.h>
#include <cuda_fp16.h>
#include <cfloat>
#include <cstdint>

#define B_   16
#define N_   4096
#define D_   1024
#define H_   512
#define O_   4096
#define KSEL 200
#define TOK  (B_ * N_)        // 65536
#define RTOT (B_ * KSEL)      // 3200 output rows
#define CMAX 320
#define RSEL 256              // radix threshold rank
#define CT64 5                // CMAX/64 tiles for exact rescore
#define NPART 8               // exact raw partials: 4 hq x 2 khalf

// Scratch globals (no cudaMalloc allowed)
__device__ float  g_part[4 * TOK];            // approx score partials per h-quarter
__device__ int    g_cand[B_ * CMAX];
__device__ int    g_ccount[B_];
__device__ float  g_cpart[4 * B_ * CMAX];     // exact per-hq score partials
__device__ int    g_topk[B_ * KSEL];
__device__ float  g_cdot[(size_t)NPART * B_ * CMAX * 128];  // raw dot partials
__device__ __half g_w1h[H_ * D_];             // W1 in fp16 (approx stage)
__device__ __half g_wphi[O_ * D_];            // Wp hi/lo split
__device__ __half g_wplo[O_ * D_];
__device__ __half g_xhi[RTOT * D_];           // gathered selected rows hi/lo
__device__ __half g_xlo[RTOT * D_];

// ---------------- helpers ----------------
__device__ __forceinline__ uint32_t smem_u32(const void* p) {
    uint32_t a;
    asm("{ .reg .u64 t; cvta.to.shared.u64 t, %1; cvt.u32.u64 %0, t; }" : "=r"(a) : "l"(p));
    return a;
}
__device__ __forceinline__ float gelu_exact(float v) {
    return 0.5f * v * (1.0f + erff(v * 0.70710678118654752440f));
}
// fast gelu: only used for candidate SELECTION (rank margin 56 >> err)
__device__ __forceinline__ float gelu_fast(float v) {
    return __fdividef(v, 1.0f + __expf(-1.702f * v));
}
__device__ __forceinline__ void ldsm4(uint32_t* r, uint32_t addr) {
    asm volatile("ldmatrix.sync.aligned.m8n8.x4.shared.b16 {%0,%1,%2,%3}, [%4];"
                 : "=r"(r[0]), "=r"(r[1]), "=r"(r[2]), "=r"(r[3]) : "r"(addr));
}
__device__ __forceinline__ void mma16816(float* c, const uint32_t* a, const uint32_t* b) {
    asm volatile("mma.sync.aligned.m16n8k16.row.col.f32.f16.f16.f32 "
                 "{%0,%1,%2,%3}, {%4,%5,%6,%7}, {%8,%9}, {%0,%1,%2,%3};"
                 : "+f"(c[0]), "+f"(c[1]), "+f"(c[2]), "+f"(c[3])
                 : "r"(a[0]), "r"(a[1]), "r"(a[2]), "r"(a[3]), "r"(b[0]), "r"(b[1]));
}
__device__ __forceinline__ void cpa16(uint32_t dst, const void* src) {
    asm volatile("cp.async.cg.shared.global [%0], [%1], 16;" :: "r"(dst), "l"(src));
}
#define CP_COMMIT() asm volatile("cp.async.commit_group;" ::: "memory")
#define CP_WAIT1()  asm volatile("cp.async.wait_group 1;" ::: "memory")
#define CP_WAIT2()  asm volatile("cp.async.wait_group 2;" ::: "memory")
// f32x2 packed FMA helpers
__device__ __forceinline__ unsigned long long pack2(float lo, float hi) {
    unsigned long long r;
    asm("mov.b64 %0, {%1, %2};" : "=l"(r) : "f"(lo), "f"(hi));
    return r;
}
__device__ __forceinline__ void unpack2(unsigned long long v, float& lo, float& hi) {
    asm("mov.b64 {%0, %1}, %2;" : "=f"(lo), "=f"(hi) : "l"(v));
}
__device__ __forceinline__ void fma2(unsigned long long& c, unsigned long long a,
                                     unsigned long long b) {
    asm("fma.rn.f32x2 %0, %1, %2, %0;" : "+l"(c) : "l"(a), "l"(b));
}

#define TSTRIDE 80                // 64B data + 16B pad (conflict-free ldmatrix)
#define TILESZ  (128 * TSTRIDE)   // 10240 bytes
#define APPROX_SMEM (2 * 2 * TILESZ + 2048)   // 2 stages x (A+B) + red = 43KB
#define PROJ_SMEM   (2 * 4 * TILESZ)          // 2 stages x (Ahi,Alo,Bhi,Blo) = 80KB

// =====================================================================
// Convert kernel: W1->fp16, Wp->hi/lo (x converted inline in approx)
// =====================================================================
__global__ void __launch_bounds__(256)
conv_w_kernel(const float* __restrict__ W1, const float* __restrict__ Wp) {
    const int bid = blockIdx.x, t = threadIdx.x;
    if (bid < H_) {
        const size_t base = (size_t)bid * D_ + 4 * t;
        const float4 v = *(const float4*)(W1 + base);
        const __half2 h0 = __floats2half2_rn(v.x, v.y), h1 = __floats2half2_rn(v.z, v.w);
        *(uint2*)&g_w1h[base] = make_uint2(*(const uint32_t*)&h0, *(const uint32_t*)&h1);
    } else {
        const size_t base = (size_t)(bid - H_) * D_ + 4 * t;
        const float4 v = *(const float4*)(Wp + base);
        const __half2 h0 = __floats2half2_rn(v.x, v.y), h1 = __floats2half2_rn(v.z, v.w);
        const float2 f0 = __half22float2(h0), f1 = __half22float2(h1);
        const __half2 l0 = __floats2half2_rn(v.x - f0.x, v.y - f0.y);
        const __half2 l1 = __floats2half2_rn(v.z - f1.x, v.w - f1.y);
        *(uint2*)&g_wphi[base] = make_uint2(*(const uint32_t*)&h0, *(const uint32_t*)&h1);
        *(uint2*)&g_wplo[base] = make_uint2(*(const uint32_t*)&l0, *(const uint32_t*)&l1);
    }
}

__global__ void __launch_bounds__(256)
gather_conv_kernel(const float* __restrict__ x) {
    const int r = blockIdx.x, t = threadIdx.x;
    const int b = r / KSEL;
    const int tok = g_topk[r];
    const float4 v = *(const float4*)(x + ((size_t)b * N_ + tok) * D_ + 4 * t);
    const __half2 h0 = __floats2half2_rn(v.x, v.y), h1 = __floats2half2_rn(v.z, v.w);
    const float2 f0 = __half22float2(h0), f1 = __half22float2(h1);
    const __half2 l0 = __floats2half2_rn(v.x - f0.x, v.y - f0.y);
    const __half2 l1 = __floats2half2_rn(v.z - f1.x, v.w - f1.y);
    *(uint2*)&g_xhi[(size_t)r * D_ + 4 * t] = make_uint2(*(const uint32_t*)&h0, *(const uint32_t*)&h1);
    *(uint2*)&g_xlo[(size_t)r * D_ + 4 * t] = make_uint2(*(const uint32_t*)&l0, *(const uint32_t*)&l1);
}

// =====================================================================
// Kernel 1: approx scores via fp16 HMMA
// A: fp32 LDG + inline cvt + STS (register buffer)
// B: 2-stage cp.async from precomputed g_w1h; 2 CTAs/SM
// grid (4 hq, 512 m-tiles), 256 thr
// =====================================================================
__global__ void __launch_bounds__(256, 2)
approx_score_kernel(const float* __restrict__ x,
                    const float* __restrict__ b1, const float* __restrict__ W2) {
    extern __shared__ __align__(16) unsigned char dsm[];
    float* red = (float*)(dsm + 2 * 2 * TILESZ);   // [128][4]

    const int t = threadIdx.x, lane = t & 31, w = t >> 5;
    const int hq = blockIdx.x, m0 = blockIdx.y * 128;
    const int wm = w & 1, wn = w >> 1;
    const int lrow = t >> 1;
    const float*  Axf  = x + (size_t)(m0 + lrow) * D_ + (t & 1) * 16;
    const __half* Bsrc = g_w1h + (size_t)(hq * 128 + lrow) * D_ + (t & 1) * 16;
    const uint32_t smb   = smem_u32(dsm);
    const uint32_t stoff = (uint32_t)lrow * TSTRIDE + (t & 1) * 32;

    float4 av[4];
    auto ldA = [&](int c) {
#pragma unroll
        for (int q = 0; q < 4; q++) av[q] = *(const float4*)(Axf + c * 32 + 4 * q);
    };
    auto stA = [&](int s) {
        uint32_t h[8];
#pragma unroll
        for (int q = 0; q < 4; q++) {
            const __half2 p0 = __floats2half2_rn(av[q].x, av[q].y);
            const __half2 p1 = __floats2half2_rn(av[q].z, av[q].w);
            h[2 * q]     = *(const uint32_t*)&p0;
            h[2 * q + 1] = *(const uint32_t*)&p1;
        }
        unsigned char* d = dsm + (size_t)s * 2 * TILESZ + stoff;
        *(uint4*)(d)      = make_uint4(h[0], h[1], h[2], h[3]);
        *(uint4*)(d + 16) = make_uint4(h[4], h[5], h[6], h[7]);
    };
    auto issueB = [&](int c, int s) {
        const uint32_t d = smb + (uint32_t)s * 2 * TILESZ + TILESZ + stoff;
        cpa16(d,      Bsrc + c * 32);
        cpa16(d + 16, Bsrc + c * 32 + 8);
    };

    // prologue: chunks 0,1 into slots 0,1; av <- chunk 2
    ldA(0); stA(0);
    issueB(0, 0); CP_COMMIT();
    ldA(1); stA(1);
    issueB(1, 1); CP_COMMIT();
    ldA(2);

    float c[4][4][4];
#pragma unroll
    for (int mi = 0; mi < 4; mi++)
#pragma unroll
        for (int nj = 0; nj < 4; nj++)
#pragma unroll
            for (int e = 0; e < 4; e++) c[mi][nj][e] = 0.0f;

    for (int j = 0; j < 32; j++) {
        CP_WAIT1();
        __syncthreads();
        const int slot = j & 1;
        const uint32_t Abase = smb + (uint32_t)slot * 2 * TILESZ;
        const uint32_t Bbase = Abase + TILESZ;
#pragma unroll
        for (int ks = 0; ks < 2; ks++) {
            const int k0h = ks * 16;
            uint32_t Af[4][4], Bf[2][4];
#pragma unroll
            for (int mi = 0; mi < 4; mi++)
                ldsm4(Af[mi], Abase + (uint32_t)(64 * wm + 16 * mi + (lane & 7) + 8 * ((lane >> 3) & 1)) * TSTRIDE
                              + (uint32_t)(k0h + 8 * (lane >> 4)) * 2);
#pragma unroll
            for (int np = 0; np < 2; np++)
                ldsm4(Bf[np], Bbase + (uint32_t)(32 * wn + 16 * np + (lane & 7) + 8 * (lane >> 4)) * TSTRIDE
                              + (uint32_t)(k0h + 8 * ((lane >> 3) & 1)) * 2);
#pragma unroll
            for (int mi = 0; mi < 4; mi++)
#pragma unroll
                for (int nj = 0; nj < 4; nj++)
                    mma16816(c[mi][nj], Af[mi], &Bf[nj >> 1][(nj & 1) * 2]);
        }
        __syncthreads();   // all warps done reading this slot before overwrite
        if (j + 2 < 32) {
            stA(slot);                     // av = chunk j+2 -> slot (j+2)&1 == slot
            if (j + 3 < 32) ldA(j + 3);
            issueB(j + 2, slot);
        }
        CP_COMMIT();
    }

    // epilogue: +b1, fast-gelu, .W2 -> per-row partial
    float pr[4][2];
#pragma unroll
    for (int mi = 0; mi < 4; mi++) { pr[mi][0] = 0.0f; pr[mi][1] = 0.0f; }
#pragma unroll
    for (int mi = 0; mi < 4; mi++)
#pragma unroll
        for (int nj = 0; nj < 4; nj++)
#pragma unroll
            for (int e = 0; e < 4; e++) {
                const int h = hq * 128 + 32 * wn + 8 * nj + 2 * (lane & 3) + (e & 1);
                const float v = c[mi][nj][e] + __ldg(&b1[h]);
                pr[mi][e >> 1] += gelu_fast(v) * __ldg(&W2[h]);
            }
    __syncthreads();
#pragma unroll
    for (int mi = 0; mi < 4; mi++)
#pragma unroll
        for (int rh = 0; rh < 2; rh++) {
            float p = pr[mi][rh];
            p += __shfl_xor_sync(0xffffffffu, p, 1);
            p += __shfl_xor_sync(0xffffffffu, p, 2);
            if ((lane & 3) == 0) red[(64 * wm + 16 * mi + (lane >> 2) + 8 * rh) * 4 + wn] = p;
        }
    __syncthreads();
    if (t < 128)
        g_part[hq * TOK + m0 + t] = red[t * 4 + 0] + red[t * 4 + 1] + red[t * 4 + 2] + red[t * 4 + 3];
}

// =====================================================================
// Kernel 2: per-batch radix-select threshold at rank RSEL (1024 threads)
// =====================================================================
__global__ void __launch_bounds__(1024)
radix_cand_kernel() {
    __shared__ uint32_t key[N_];
    __shared__ int hist[256];
    __shared__ uint32_t s_prefix;
    __shared__ int s_remaining, s_cnt;
    const int b = blockIdx.x, t = threadIdx.x;

    for (int i = t; i < N_; i += 1024) {
        const int g = b * N_ + i;
        const float s = g_part[g] + g_part[TOK + g] + g_part[2 * TOK + g] + g_part[3 * TOK + g];
        const uint32_t u = __float_as_uint(s);
        key[i] = (u & 0x80000000u) ? ~u : (u | 0x80000000u);
    }
    if (t == 0) { s_prefix = 0; s_remaining = RSEL; s_cnt = 0; }
    __syncthreads();

    for (int pass = 0; pass < 3; pass++) {
        const int shift = 24 - pass * 8;
        if (t < 256) hist[t] = 0;
        __syncthreads();
        const uint32_t pref = s_prefix;
        for (int i = t; i < N_; i += 1024) {
            const uint32_t k = key[i];
            const bool match = (pass == 0) || ((k >> (shift + 8)) == pref);
            if (match) atomicAdd(&hist[(k >> shift) & 255], 1);
        }
        __syncthreads();
        if (t == 0) {
            int rem = s_remaining, acc = 0, v = 255;
            for (; v > 0; v--) { if (acc + hist[v] >= rem) break; acc += hist[v]; }
            s_prefix = (pref << 8) | (uint32_t)v;
            s_remaining = rem - acc;
        }
        __syncthreads();
    }

    const uint32_t thr = s_prefix;
    for (int i = t; i < N_; i += 1024) {
        if ((key[i] >> 8) >= thr) {
            const int pos = atomicAdd(&s_cnt, 1);
            if (pos < CMAX) g_cand[b * CMAX + pos] = i;
        }
    }
    __syncthreads();
    const int cnt = min(s_cnt, CMAX);
    if (t == 0) g_ccount[b] = cnt;
    for (int i = cnt + t; i < CMAX; i += 1024) g_cand[b * CMAX + i] = 0;
}

// =====================================================================
// Kernel 3: exact fp32 rescoring, 64 cand x 128 h x 512 k per CTA
// grid (CT64, 8, B_): blockIdx.y = hq*2 + khalf -> 640 CTAs, 3/SM
// thread = 4 cand x 8 h; Bs[k][h-chunk padded to 10] -> conflict-free
// (R11-measured layout: 138.7us)
// =====================================================================
#define ASTR 36    // As row stride (32 data + 4 pad, 144B 16B-aligned)
#define BSTR 160   // Bs row stride in floats (16 chunks x 10)
__global__ void __launch_bounds__(256, 3)
exact_score_kernel(const float* __restrict__ x, const float* __restrict__ W1) {
    const int ct = blockIdx.x, yb = blockIdx.y, b = blockIdx.z;
    const int hq = yb >> 1, kh = yb & 1;
    if (ct * 64 >= g_ccount[b]) return;

    __shared__ __align__(16) float As[64][ASTR];   // [cand][k]
    __shared__ __align__(16) float Bs[32][BSTR];   // [k][h-chunk*10]
    __shared__ int cidx[64];
    const int t = threadIdx.x;
    if (t < 64) cidx[t] = g_cand[b * CMAX + ct * 64 + t];
    __syncthreads();

    const int cg = t >> 4;        // 0..15 candidate group (4 cand each)
    const int hg = t & 15;        // 0..15 h group (8 h each)
    const int cb = cg * 4;

    // loaders
    const int arow = t >> 2, acol = (t & 3) * 8;
    const int bh   = t >> 1, bks = (t & 1) * 16;
    const float* Agr = x  + ((size_t)b * N_ + cidx[arow]) * D_ + kh * 512 + acol;
    const float* Bgr = W1 + (size_t)(hq * 128 + bh) * D_ + kh * 512 + bks;
    const int bchunk = bh >> 3, blane = bh & 7;

    unsigned long long acc[4][4];   // [cand][h-pair]
#pragma unroll
    for (int ci = 0; ci < 4; ci++)
#pragma unroll
        for (int j = 0; j < 4; j++) acc[ci][j] = pack2(0.0f, 0.0f);

    for (int k0 = 0; k0 < 512; k0 += 32) {
        const float4 a0 = *(const float4*)(Agr + k0);
        const float4 a1 = *(const float4*)(Agr + k0 + 4);
        float4 bw[4];
#pragma unroll
        for (int q = 0; q < 4; q++) bw[q] = *(const float4*)(Bgr + k0 + 4 * q);
        __syncthreads();
        *(float4*)&As[arow][acol]     = a0;
        *(float4*)&As[arow][acol + 4] = a1;
#pragma unroll
        for (int q = 0; q < 4; q++) {
            Bs[bks + 4 * q + 0][bchunk * 10 + blane] = bw[q].x;
            Bs[bks + 4 * q + 1][bchunk * 10 + blane] = bw[q].y;
            Bs[bks + 4 * q + 2][bchunk * 10 + blane] = bw[q].z;
            Bs[bks + 4 * q + 3][bchunk * 10 + blane] = bw[q].w;
        }
        __syncthreads();
#pragma unroll
        for (int kk = 0; kk < 32; kk++) {
            const unsigned long long* brow = (const unsigned long long*)&Bs[kk][hg * 10];
            const unsigned long long b0 = brow[0], b1v = brow[1], b2 = brow[2], b3 = brow[3];
#pragma unroll
            for (int ci = 0; ci < 4; ci++) {
                const float avv = As[cb + ci][kk];
                const unsigned long long aa = pack2(avv, avv);
                fma2(acc[ci][0], aa, b0); fma2(acc[ci][1], aa, b1v);
                fma2(acc[ci][2], aa, b2); fma2(acc[ci][3], aa, b3);
            }
        }
    }

    // write raw 8-h dot partials per thread to g_cdot (combine applies gelu)
#pragma unroll
    for (int ci = 0; ci < 4; ci++) {
#pragma unroll
        for (int j = 0; j < 4; j++) {
            float c0, c1;
            unpack2(acc[ci][j], c0, c1);
            const size_t base = ((((size_t)yb * B_ + b) * CMAX) + ct * 64 + cb + ci) * 128
                                + hg * 8 + 2 * j;
            g_cdot[base]     = c0;
            g_cdot[base + 1] = c1;
        }
    }
}

// =====================================================================
// Kernel 3b: combine k-halves, apply exact gelu.W2 -> per-hq partials
// grid (B_, 4): CTA = (batch, h-quarter); 64 CTAs total
// =====================================================================
__global__ void __launch_bounds__(256)
exact_combine_kernel(const float* __restrict__ b1, const float* __restrict__ W2) {
    __shared__ float sb1[128], sw2[128];
    const int b = blockIdx.x, hq = blockIdx.y, t = threadIdx.x;
    if (t < 128) { sb1[t] = b1[hq * 128 + t]; sw2[t] = W2[hq * 128 + t]; }
    __syncthreads();
    const int cnt = g_ccount[b];
    for (int i = t; i < cnt; i += 256) {
        const size_t p0 = ((((size_t)(hq * 2 + 0) * B_ + b) * CMAX) + i) * 128;
        const size_t p1 = ((((size_t)(hq * 2 + 1) * B_ + b) * CMAX) + i) * 128;
        float s = 0.0f;
        for (int hh = 0; hh < 128; hh += 4) {
            const float4 d0 = *(const float4*)&g_cdot[p0 + hh];
            const float4 d1 = *(const float4*)&g_cdot[p1 + hh];
            s += gelu_exact(d0.x + d1.x + sb1[hh])     * sw2[hh];
            s += gelu_exact(d0.y + d1.y + sb1[hh + 1]) * sw2[hh + 1];
            s += gelu_exact(d0.z + d1.z + sb1[hh + 2]) * sw2[hh + 2];
            s += gelu_exact(d0.w + d1.w + sb1[hh + 3]) * sw2[hh + 3];
        }
        g_cpart[((size_t)hq * B_ + b) * CMAX + i] = s;
    }
}

// =====================================================================
// Kernel 4: rank-by-counting final top-200 (fully parallel, deterministic)
// =====================================================================
__global__ void __launch_bounds__(256)
final_topk_kernel() {
    __shared__ float cs[CMAX];
    __shared__ int   cid[CMAX];
    const int b = blockIdx.x, t = threadIdx.x;
    const int cnt = g_ccount[b];

    for (int i = t; i < CMAX; i += 256) {
        if (i < cnt) {
            float s = 0.0f;
#pragma unroll
            for (int hq = 0; hq < 4; hq++)
                s += g_cpart[((size_t)hq * B_ + b) * CMAX + i];
            cs[i] = s; cid[i] = g_cand[b * CMAX + i];
        } else { cs[i] = -FLT_MAX; cid[i] = 0x7fffffff; }
    }
    __syncthreads();

    for (int i = t; i < CMAX; i += 256) {
        const float si = cs[i];
        const int idi = cid[i];
        if (idi == 0x7fffffff) continue;
        int rank = 0;
#pragma unroll 8
        for (int j = 0; j < CMAX; j++) {
            const float sj = cs[j];
            rank += (sj > si) || (sj == si && cid[j] < idi);
        }
        if (rank < KSEL) g_topk[b * KSEL + rank] = idi;
    }
}

// =====================================================================
// Kernel 5: projection, 2-stage cp.async pipeline, 2 CTAs/SM, 3-mma split
// grid (32 o-tiles, 25 row-tiles), 256 thr, 80KB dynamic smem
// =====================================================================
__global__ void __launch_bounds__(256, 2)
proj_kernel(const float* __restrict__ bp, float* __restrict__ out) {
    extern __shared__ __align__(16) unsigned char dsm[];   // [2][4][TILESZ]

    const int t = threadIdx.x, lane = t & 31, w = t >> 5;
    const int wm = w & 1, wn = w >> 1;
    const int o0 = blockIdx.x * 128, r0 = blockIdx.y * 128;
    const int lrow = t >> 1;

    const __half* Ahg = g_xhi  + (size_t)(r0 + lrow) * D_ + (t & 1) * 16;
    const __half* Alg = g_xlo  + (size_t)(r0 + lrow) * D_ + (t & 1) * 16;
    const __half* Bhg = g_wphi + (size_t)(o0 + lrow) * D_ + (t & 1) * 16;
    const __half* Blg = g_wplo + (size_t)(o0 + lrow) * D_ + (t & 1) * 16;
    const uint32_t smb   = smem_u32(dsm);
    const uint32_t stoff = (uint32_t)lrow * TSTRIDE + (t & 1) * 32;

    auto issue = [&](int c, int s) {
        const uint32_t d = smb + (uint32_t)s * 4 * TILESZ + stoff;
        cpa16(d,                   Ahg + c * 32);
        cpa16(d + 16,              Ahg + c * 32 + 8);
        cpa16(d + TILESZ,          Alg + c * 32);
        cpa16(d + TILESZ + 16,     Alg + c * 32 + 8);
        cpa16(d + 2 * TILESZ,      Bhg + c * 32);
        cpa16(d + 2 * TILESZ + 16, Bhg + c * 32 + 8);
        cpa16(d + 3 * TILESZ,      Blg + c * 32);
        cpa16(d + 3 * TILESZ + 16, Blg + c * 32 + 8);
    };
    issue(0, 0); CP_COMMIT();
    issue(1, 1); CP_COMMIT();

    float c[4][4][4];
#pragma unroll
    for (int mi = 0; mi < 4; mi++)
#pragma unroll
        for (int nj = 0; nj < 4; nj++)
#pragma unroll
            for (int e = 0; e < 4; e++) c[mi][nj][e] = 0.0f;

    for (int j = 0; j < 32; j++) {
        CP_WAIT1();
        __syncthreads();
        const int slot = j & 1;
        const uint32_t Ahi = smb + (uint32_t)slot * 4 * TILESZ;
        const uint32_t Alo = Ahi + TILESZ;
        const uint32_t Bhi = Ahi + 2 * TILESZ;
        const uint32_t Blo = Ahi + 3 * TILESZ;
        const uint32_t aoff = (uint32_t)(64 * wm + (lane & 7) + 8 * ((lane >> 3) & 1)) * TSTRIDE + (uint32_t)(8 * (lane >> 4)) * 2;
        const uint32_t boff = (uint32_t)(32 * wn + (lane & 7) + 8 * (lane >> 4)) * TSTRIDE + (uint32_t)(8 * ((lane >> 3) & 1)) * 2;
#pragma unroll
        for (int ks = 0; ks < 2; ks++) {
            const uint32_t kb = (uint32_t)(ks * 16) * 2;
            uint32_t Ah[4][4], Al[4][4], Bh[2][4], Bl[2][4];
#pragma unroll
            for (int mi = 0; mi < 4; mi++) {
                ldsm4(Ah[mi], Ahi + aoff + (uint32_t)(16 * mi) * TSTRIDE + kb);
                ldsm4(Al[mi], Alo + aoff + (uint32_t)(16 * mi) * TSTRIDE + kb);
            }
#pragma unroll
            for (int np = 0; np < 2; np++) {
                ldsm4(Bh[np], Bhi + boff + (uint32_t)(16 * np) * TSTRIDE + kb);
                ldsm4(Bl[np], Blo + boff + (uint32_t)(16 * np) * TSTRIDE + kb);
            }
#pragma unroll
            for (int mi = 0; mi < 4; mi++)
#pragma unroll
                for (int nj = 0; nj < 4; nj++) {
                    mma16816(c[mi][nj], Ah[mi], &Bh[nj >> 1][(nj & 1) * 2]);
                    mma16816(c[mi][nj], Ah[mi], &Bl[nj >> 1][(nj & 1) * 2]);
                    mma16816(c[mi][nj], Al[mi], &Bh[nj >> 1][(nj & 1) * 2]);
                }
        }
        __syncthreads();   // all warps done reading this slot before overwrite
        if (j + 2 < 32) issue(j + 2, slot);
        CP_COMMIT();
    }

#pragma unroll
    for (int mi = 0; mi < 4; mi++)
#pragma unroll
        for (int nj = 0; nj < 4; nj++)
#pragma unroll
            for (int rh = 0; rh < 2; rh++) {
                const int R  = r0 + 64 * wm + 16 * mi + (lane >> 2) + 8 * rh;
                const int oc = o0 + 32 * wn + 8 * nj + 2 * (lane & 3);
                float2 v;
                v.x = c[mi][nj][2 * rh + 0] + __ldg(&bp[oc]);
                v.y = c[mi][nj][2 * rh + 1] + __ldg(&bp[oc + 1]);
                *(float2*)(out + (size_t)R * O_ + oc) = v;
            }
}

// =====================================================================
// Entry point
// =====================================================================
extern "C" void kernel_launch(void* const* d_in, const int* in_sizes, int n_in,
                              void* d_out, int out_size) {
    (void)in_sizes; (void)n_in; (void)out_size;
    const float* x  = (const float*)d_in[0];
    const float* W1 = (const float*)d_in[1];
    const float* b1 = (const float*)d_in[2];
    const float* W2 = (const float*)d_in[3];
    // d_in[4] = b2: constant shift, irrelevant to topk ordering
    const float* Wp = (const float*)d_in[5];
    const float* bp = (const float*)d_in[6];
    float* out = (float*)d_out;

    cudaFuncSetAttribute(approx_score_kernel, cudaFuncAttributeMaxDynamicSharedMemorySize, APPROX_SMEM);
    cudaFuncSetAttribute(proj_kernel,         cudaFuncAttributeMaxDynamicSharedMemorySize, PROJ_SMEM);

    conv_w_kernel<<<H_ + O_, 256>>>(W1, Wp);
    approx_score_kernel<<<dim3(4, TOK / 128), 256, APPROX_SMEM>>>(x, b1, W2);
    radix_cand_kernel<<<B_, 1024>>>();
    exact_score_kernel<<<dim3(CT64, 8, B_), 256>>>(x, W1);
    exact_combine_kernel<<<dim3(B_, 4), 256>>>(b1, W2);
    final_topk_kernel<<<B_, 256>>>();
    gather_conv_kernel<<<RTOT, 256>>>(x);
    proj_kernel<<<dim3(O_ / 128, RTOT / 128), 256, PROJ_SMEM>>>(bp, out);
}

// round 16
// speedup vs baseline: 1.0315x; 1.0315x over previous
#include <cuda_runtime.h>
#include <cuda_fp16.h>
#include <cfloat>
#include <cstdint>

#define B_   16
#define N_   4096
#define D_   1024
#define H_   512
#define O_   4096
#define KSEL 200
#define TOK  (B_ * N_)        // 65536
#define RTOT (B_ * KSEL)      // 3200 output rows
#define CMAX 320
#define RSEL 256              // radix threshold rank
#define CT64 5                // CMAX/64 tiles for exact rescore
#define NPART 16              // exact raw partials: 4 hq x 4 kquarter

// Scratch globals (no cudaMalloc allowed)
__device__ float  g_part[4 * TOK];            // approx score partials per h-quarter
__device__ int    g_cand[B_ * CMAX];
__device__ int    g_ccount[B_];
__device__ float  g_cpart[4 * B_ * CMAX];     // exact per-hq score partials
__device__ int    g_topk[B_ * KSEL];
__device__ float  g_cdot[(size_t)NPART * B_ * CMAX * 128];  // raw dot partials
__device__ __half g_w1h[H_ * D_];             // W1 in fp16 (approx stage)
__device__ __half g_wphi[O_ * D_];            // Wp hi/lo split
__device__ __half g_wplo[O_ * D_];
__device__ __half g_xhi[RTOT * D_];           // gathered selected rows hi/lo
__device__ __half g_xlo[RTOT * D_];

// ---------------- helpers ----------------
__device__ __forceinline__ uint32_t smem_u32(const void* p) {
    uint32_t a;
    asm("{ .reg .u64 t; cvta.to.shared.u64 t, %1; cvt.u32.u64 %0, t; }" : "=r"(a) : "l"(p));
    return a;
}
__device__ __forceinline__ float gelu_exact(float v) {
    return 0.5f * v * (1.0f + erff(v * 0.70710678118654752440f));
}
// fast gelu: only used for candidate SELECTION (rank margin 56 >> err)
__device__ __forceinline__ float gelu_fast(float v) {
    return __fdividef(v, 1.0f + __expf(-1.702f * v));
}
__device__ __forceinline__ void ldsm4(uint32_t* r, uint32_t addr) {
    asm volatile("ldmatrix.sync.aligned.m8n8.x4.shared.b16 {%0,%1,%2,%3}, [%4];"
                 : "=r"(r[0]), "=r"(r[1]), "=r"(r[2]), "=r"(r[3]) : "r"(addr));
}
__device__ __forceinline__ void mma16816(float* c, const uint32_t* a, const uint32_t* b) {
    asm volatile("mma.sync.aligned.m16n8k16.row.col.f32.f16.f16.f32 "
                 "{%0,%1,%2,%3}, {%4,%5,%6,%7}, {%8,%9}, {%0,%1,%2,%3};"
                 : "+f"(c[0]), "+f"(c[1]), "+f"(c[2]), "+f"(c[3])
                 : "r"(a[0]), "r"(a[1]), "r"(a[2]), "r"(a[3]), "r"(b[0]), "r"(b[1]));
}
__device__ __forceinline__ void cpa16(uint32_t dst, const void* src) {
    asm volatile("cp.async.cg.shared.global [%0], [%1], 16;" :: "r"(dst), "l"(src));
}
#define CP_COMMIT() asm volatile("cp.async.commit_group;" ::: "memory")
#define CP_WAIT1()  asm volatile("cp.async.wait_group 1;" ::: "memory")
#define CP_WAIT2()  asm volatile("cp.async.wait_group 2;" ::: "memory")
// f32x2 packed FMA helpers
__device__ __forceinline__ unsigned long long pack2(float lo, float hi) {
    unsigned long long r;
    asm("mov.b64 %0, {%1, %2};" : "=l"(r) : "f"(lo), "f"(hi));
    return r;
}
__device__ __forceinline__ void unpack2(unsigned long long v, float& lo, float& hi) {
    asm("mov.b64 {%0, %1}, %2;" : "=f"(lo), "=f"(hi) : "l"(v));
}
__device__ __forceinline__ void fma2(unsigned long long& c, unsigned long long a,
                                     unsigned long long b) {
    asm("fma.rn.f32x2 %0, %1, %2, %0;" : "+l"(c) : "l"(a), "l"(b));
}

#define TSTRIDE 80                // 64B data + 16B pad (conflict-free ldmatrix)
#define TILESZ  (128 * TSTRIDE)   // 10240 bytes
#define APPROX_SMEM (4 * 2 * TILESZ + 2048)   // 4 stages x (A+B) + red
#define PROJ_SMEM   (2 * 4 * TILESZ)          // 2 stages x (Ahi,Alo,Bhi,Blo) = 80KB

// =====================================================================
// Convert kernel: W1->fp16, Wp->hi/lo (x converted inline in approx)
// =====================================================================
__global__ void __launch_bounds__(256)
conv_w_kernel(const float* __restrict__ W1, const float* __restrict__ Wp) {
    const int bid = blockIdx.x, t = threadIdx.x;
    if (bid < H_) {
        const size_t base = (size_t)bid * D_ + 4 * t;
        const float4 v = *(const float4*)(W1 + base);
        const __half2 h0 = __floats2half2_rn(v.x, v.y), h1 = __floats2half2_rn(v.z, v.w);
        *(uint2*)&g_w1h[base] = make_uint2(*(const uint32_t*)&h0, *(const uint32_t*)&h1);
    } else {
        const size_t base = (size_t)(bid - H_) * D_ + 4 * t;
        const float4 v = *(const float4*)(Wp + base);
        const __half2 h0 = __floats2half2_rn(v.x, v.y), h1 = __floats2half2_rn(v.z, v.w);
        const float2 f0 = __half22float2(h0), f1 = __half22float2(h1);
        const __half2 l0 = __floats2half2_rn(v.x - f0.x, v.y - f0.y);
        const __half2 l1 = __floats2half2_rn(v.z - f1.x, v.w - f1.y);
        *(uint2*)&g_wphi[base] = make_uint2(*(const uint32_t*)&h0, *(const uint32_t*)&h1);
        *(uint2*)&g_wplo[base] = make_uint2(*(const uint32_t*)&l0, *(const uint32_t*)&l1);
    }
}

__global__ void __launch_bounds__(256)
gather_conv_kernel(const float* __restrict__ x) {
    const int r = blockIdx.x, t = threadIdx.x;
    const int b = r / KSEL;
    const int tok = g_topk[r];
    const float4 v = *(const float4*)(x + ((size_t)b * N_ + tok) * D_ + 4 * t);
    const __half2 h0 = __floats2half2_rn(v.x, v.y), h1 = __floats2half2_rn(v.z, v.w);
    const float2 f0 = __half22float2(h0), f1 = __half22float2(h1);
    const __half2 l0 = __floats2half2_rn(v.x - f0.x, v.y - f0.y);
    const __half2 l1 = __floats2half2_rn(v.z - f1.x, v.w - f1.y);
    *(uint2*)&g_xhi[(size_t)r * D_ + 4 * t] = make_uint2(*(const uint32_t*)&h0, *(const uint32_t*)&h1);
    *(uint2*)&g_xlo[(size_t)r * D_ + 4 * t] = make_uint2(*(const uint32_t*)&l0, *(const uint32_t*)&l1);
}

// =====================================================================
// Kernel 1: approx scores via fp16 HMMA  (R13-measured version)
// A: fp32 LDG + inline cvt + STS (register double-buffer)
// B: 4-stage cp.async from precomputed g_w1h
// grid (4 hq, 512 m-tiles), 256 thr
// =====================================================================
__global__ void __launch_bounds__(256)
approx_score_kernel(const float* __restrict__ x,
                    const float* __restrict__ b1, const float* __restrict__ W2) {
    extern __shared__ __align__(16) unsigned char dsm[];
    float* red = (float*)(dsm + 4 * 2 * TILESZ);   // [128][4]

    const int t = threadIdx.x, lane = t & 31, w = t >> 5;
    const int hq = blockIdx.x, m0 = blockIdx.y * 128;
    const int wm = w & 1, wn = w >> 1;
    const int lrow = t >> 1;
    const float*  Axf  = x + (size_t)(m0 + lrow) * D_ + (t & 1) * 16;
    const __half* Bsrc = g_w1h + (size_t)(hq * 128 + lrow) * D_ + (t & 1) * 16;
    const uint32_t smb   = smem_u32(dsm);
    const uint32_t stoff = (uint32_t)lrow * TSTRIDE + (t & 1) * 32;

    float4 av[4];
    auto ldA = [&](int c) {
#pragma unroll
        for (int q = 0; q < 4; q++) av[q] = *(const float4*)(Axf + c * 32 + 4 * q);
    };
    auto stA = [&](int s) {
        uint32_t h[8];
#pragma unroll
        for (int q = 0; q < 4; q++) {
            const __half2 p0 = __floats2half2_rn(av[q].x, av[q].y);
            const __half2 p1 = __floats2half2_rn(av[q].z, av[q].w);
            h[2 * q]     = *(const uint32_t*)&p0;
            h[2 * q + 1] = *(const uint32_t*)&p1;
        }
        unsigned char* d = dsm + (size_t)s * 2 * TILESZ + stoff;
        *(uint4*)(d)      = make_uint4(h[0], h[1], h[2], h[3]);
        *(uint4*)(d + 16) = make_uint4(h[4], h[5], h[6], h[7]);
    };
    auto issueB = [&](int c, int s) {
        const uint32_t d = smb + (uint32_t)s * 2 * TILESZ + TILESZ + stoff;
        cpa16(d,      Bsrc + c * 32);
        cpa16(d + 16, Bsrc + c * 32 + 8);
    };

    // prologue
    ldA(0);
    issueB(0, 0); CP_COMMIT();
    issueB(1, 1); CP_COMMIT();
    issueB(2, 2); CP_COMMIT();
    stA(0);
    ldA(1);

    float c[4][4][4];
#pragma unroll
    for (int mi = 0; mi < 4; mi++)
#pragma unroll
        for (int nj = 0; nj < 4; nj++)
#pragma unroll
            for (int e = 0; e < 4; e++) c[mi][nj][e] = 0.0f;

    for (int j = 0; j < 32; j++) {
        CP_WAIT2();
        __syncthreads();
        const int slot = j & 3;
        const uint32_t Abase = smb + (uint32_t)slot * 2 * TILESZ;
        const uint32_t Bbase = Abase + TILESZ;
#pragma unroll
        for (int ks = 0; ks < 2; ks++) {
            const int k0h = ks * 16;
            uint32_t Af[4][4], Bf[2][4];
#pragma unroll
            for (int mi = 0; mi < 4; mi++)
                ldsm4(Af[mi], Abase + (uint32_t)(64 * wm + 16 * mi + (lane & 7) + 8 * ((lane >> 3) & 1)) * TSTRIDE
                              + (uint32_t)(k0h + 8 * (lane >> 4)) * 2);
#pragma unroll
            for (int np = 0; np < 2; np++)
                ldsm4(Bf[np], Bbase + (uint32_t)(32 * wn + 16 * np + (lane & 7) + 8 * (lane >> 4)) * TSTRIDE
                              + (uint32_t)(k0h + 8 * ((lane >> 3) & 1)) * 2);
#pragma unroll
            for (int mi = 0; mi < 4; mi++)
#pragma unroll
                for (int nj = 0; nj < 4; nj++)
                    mma16816(c[mi][nj], Af[mi], &Bf[nj >> 1][(nj & 1) * 2]);
        }
        if (j + 1 < 32) stA((j + 1) & 3);   // store prefetched A chunk j+1
        if (j + 2 < 32) ldA(j + 2);          // prefetch A chunk j+2
        if (j + 3 < 32) issueB(j + 3, (j + 3) & 3);
        CP_COMMIT();
    }

    // epilogue: +b1, fast-gelu, .W2 -> per-row partial
    float pr[4][2];
#pragma unroll
    for (int mi = 0; mi < 4; mi++) { pr[mi][0] = 0.0f; pr[mi][1] = 0.0f; }
#pragma unroll
    for (int mi = 0; mi < 4; mi++)
#pragma unroll
        for (int nj = 0; nj < 4; nj++)
#pragma unroll
            for (int e = 0; e < 4; e++) {
                const int h = hq * 128 + 32 * wn + 8 * nj + 2 * (lane & 3) + (e & 1);
                const float v = c[mi][nj][e] + __ldg(&b1[h]);
                pr[mi][e >> 1] += gelu_fast(v) * __ldg(&W2[h]);
            }
    __syncthreads();
#pragma unroll
    for (int mi = 0; mi < 4; mi++)
#pragma unroll
        for (int rh = 0; rh < 2; rh++) {
            float p = pr[mi][rh];
            p += __shfl_xor_sync(0xffffffffu, p, 1);
            p += __shfl_xor_sync(0xffffffffu, p, 2);
            if ((lane & 3) == 0) red[(64 * wm + 16 * mi + (lane >> 2) + 8 * rh) * 4 + wn] = p;
        }
    __syncthreads();
    if (t < 128)
        g_part[hq * TOK + m0 + t] = red[t * 4 + 0] + red[t * 4 + 1] + red[t * 4 + 2] + red[t * 4 + 3];
}

// =====================================================================
// Kernel 2: per-batch radix-select threshold at rank RSEL (1024 threads)
// =====================================================================
__global__ void __launch_bounds__(1024)
radix_cand_kernel() {
    __shared__ uint32_t key[N_];
    __shared__ int hist[256];
    __shared__ uint32_t s_prefix;
    __shared__ int s_remaining, s_cnt;
    const int b = blockIdx.x, t = threadIdx.x;

    for (int i = t; i < N_; i += 1024) {
        const int g = b * N_ + i;
        const float s = g_part[g] + g_part[TOK + g] + g_part[2 * TOK + g] + g_part[3 * TOK + g];
        const uint32_t u = __float_as_uint(s);
        key[i] = (u & 0x80000000u) ? ~u : (u | 0x80000000u);
    }
    if (t == 0) { s_prefix = 0; s_remaining = RSEL; s_cnt = 0; }
    __syncthreads();

    for (int pass = 0; pass < 3; pass++) {
        const int shift = 24 - pass * 8;
        if (t < 256) hist[t] = 0;
        __syncthreads();
        const uint32_t pref = s_prefix;
        for (int i = t; i < N_; i += 1024) {
            const uint32_t k = key[i];
            const bool match = (pass == 0) || ((k >> (shift + 8)) == pref);
            if (match) atomicAdd(&hist[(k >> shift) & 255], 1);
        }
        __syncthreads();
        if (t == 0) {
            int rem = s_remaining, acc = 0, v = 255;
            for (; v > 0; v--) { if (acc + hist[v] >= rem) break; acc += hist[v]; }
            s_prefix = (pref << 8) | (uint32_t)v;
            s_remaining = rem - acc;
        }
        __syncthreads();
    }

    const uint32_t thr = s_prefix;
    for (int i = t; i < N_; i += 1024) {
        if ((key[i] >> 8) >= thr) {
            const int pos = atomicAdd(&s_cnt, 1);
            if (pos < CMAX) g_cand[b * CMAX + pos] = i;
        }
    }
    __syncthreads();
    const int cnt = min(s_cnt, CMAX);
    if (t == 0) g_ccount[b] = cnt;
    for (int i = cnt + t; i < CMAX; i += 1024) g_cand[b * CMAX + i] = 0;
}

// =====================================================================
// Kernel 3: exact fp32 rescoring, 64 cand x 128 h x 256 k per CTA
// grid (CT64, 16, B_): blockIdx.y = hq*4 + kquarter -> 1280 CTAs, 3/SM
// thread = 4 cand x 8 h; Bs[k][h-chunk padded to 10] -> conflict-free
// (R11-measured inner layout)
// =====================================================================
#define ASTR 36    // As row stride (32 data + 4 pad, 144B 16B-aligned)
#define BSTR 160   // Bs row stride in floats (16 chunks x 10)
__global__ void __launch_bounds__(256, 3)
exact_score_kernel(const float* __restrict__ x, const float* __restrict__ W1) {
    const int ct = blockIdx.x, yb = blockIdx.y, b = blockIdx.z;
    const int hq = yb >> 2, kq = yb & 3;
    if (ct * 64 >= g_ccount[b]) return;

    __shared__ __align__(16) float As[64][ASTR];   // [cand][k]
    __shared__ __align__(16) float Bs[32][BSTR];   // [k][h-chunk*10]
    __shared__ int cidx[64];
    const int t = threadIdx.x;
    if (t < 64) cidx[t] = g_cand[b * CMAX + ct * 64 + t];
    __syncthreads();

    const int cg = t >> 4;        // 0..15 candidate group (4 cand each)
    const int hg = t & 15;        // 0..15 h group (8 h each)
    const int cb = cg * 4;

    // loaders
    const int arow = t >> 2, acol = (t & 3) * 8;
    const int bh   = t >> 1, bks = (t & 1) * 16;
    const float* Agr = x  + ((size_t)b * N_ + cidx[arow]) * D_ + kq * 256 + acol;
    const float* Bgr = W1 + (size_t)(hq * 128 + bh) * D_ + kq * 256 + bks;
    const int bchunk = bh >> 3, blane = bh & 7;

    unsigned long long acc[4][4];   // [cand][h-pair]
#pragma unroll
    for (int ci = 0; ci < 4; ci++)
#pragma unroll
        for (int j = 0; j < 4; j++) acc[ci][j] = pack2(0.0f, 0.0f);

    for (int k0 = 0; k0 < 256; k0 += 32) {
        const float4 a0 = *(const float4*)(Agr + k0);
        const float4 a1 = *(const float4*)(Agr + k0 + 4);
        float4 bw[4];
#pragma unroll
        for (int q = 0; q < 4; q++) bw[q] = *(const float4*)(Bgr + k0 + 4 * q);
        __syncthreads();
        *(float4*)&As[arow][acol]     = a0;
        *(float4*)&As[arow][acol + 4] = a1;
#pragma unroll
        for (int q = 0; q < 4; q++) {
            Bs[bks + 4 * q + 0][bchunk * 10 + blane] = bw[q].x;
            Bs[bks + 4 * q + 1][bchunk * 10 + blane] = bw[q].y;
            Bs[bks + 4 * q + 2][bchunk * 10 + blane] = bw[q].z;
            Bs[bks + 4 * q + 3][bchunk * 10 + blane] = bw[q].w;
        }
        __syncthreads();
#pragma unroll
        for (int kk = 0; kk < 32; kk++) {
            const unsigned long long* brow = (const unsigned long long*)&Bs[kk][hg * 10];
            const unsigned long long b0 = brow[0], b1v = brow[1], b2 = brow[2], b3 = brow[3];
#pragma unroll
            for (int ci = 0; ci < 4; ci++) {
                const float avv = As[cb + ci][kk];
                const unsigned long long aa = pack2(avv, avv);
                fma2(acc[ci][0], aa, b0); fma2(acc[ci][1], aa, b1v);
                fma2(acc[ci][2], aa, b2); fma2(acc[ci][3], aa, b3);
            }
        }
    }

    // write raw 8-h dot partials per thread to g_cdot (combine applies gelu)
#pragma unroll
    for (int ci = 0; ci < 4; ci++) {
#pragma unroll
        for (int j = 0; j < 4; j++) {
            float c0, c1;
            unpack2(acc[ci][j], c0, c1);
            const size_t base = ((((size_t)yb * B_ + b) * CMAX) + ct * 64 + cb + ci) * 128
                                + hg * 8 + 2 * j;
            g_cdot[base]     = c0;
            g_cdot[base + 1] = c1;
        }
    }
}

// =====================================================================
// Kernel 3b: combine k-quarters, apply exact gelu.W2 -> per-hq partials
// grid (B_, 4): CTA = (batch, h-quarter); 64 CTAs total
// =====================================================================
__global__ void __launch_bounds__(256)
exact_combine_kernel(const float* __restrict__ b1, const float* __restrict__ W2) {
    __shared__ float sb1[128], sw2[128];
    const int b = blockIdx.x, hq = blockIdx.y, t = threadIdx.x;
    if (t < 128) { sb1[t] = b1[hq * 128 + t]; sw2[t] = W2[hq * 128 + t]; }
    __syncthreads();
    const int cnt = g_ccount[b];
    for (int i = t; i < cnt; i += 256) {
        const size_t p0 = ((((size_t)(hq * 4 + 0) * B_ + b) * CMAX) + i) * 128;
        const size_t p1 = ((((size_t)(hq * 4 + 1) * B_ + b) * CMAX) + i) * 128;
        const size_t p2 = ((((size_t)(hq * 4 + 2) * B_ + b) * CMAX) + i) * 128;
        const size_t p3 = ((((size_t)(hq * 4 + 3) * B_ + b) * CMAX) + i) * 128;
        float s = 0.0f;
        for (int hh = 0; hh < 128; hh += 4) {
            const float4 d0 = *(const float4*)&g_cdot[p0 + hh];
            const float4 d1 = *(const float4*)&g_cdot[p1 + hh];
            const float4 d2 = *(const float4*)&g_cdot[p2 + hh];
            const float4 d3 = *(const float4*)&g_cdot[p3 + hh];
            s += gelu_exact(d0.x + d1.x + d2.x + d3.x + sb1[hh])     * sw2[hh];
            s += gelu_exact(d0.y + d1.y + d2.y + d3.y + sb1[hh + 1]) * sw2[hh + 1];
            s += gelu_exact(d0.z + d1.z + d2.z + d3.z + sb1[hh + 2]) * sw2[hh + 2];
            s += gelu_exact(d0.w + d1.w + d2.w + d3.w + sb1[hh + 3]) * sw2[hh + 3];
        }
        g_cpart[((size_t)hq * B_ + b) * CMAX + i] = s;
    }
}

// =====================================================================
// Kernel 4: rank-by-counting final top-200 (fully parallel, deterministic)
// =====================================================================
__global__ void __launch_bounds__(256)
final_topk_kernel() {
    __shared__ float cs[CMAX];
    __shared__ int   cid[CMAX];
    const int b = blockIdx.x, t = threadIdx.x;
    const int cnt = g_ccount[b];

    for (int i = t; i < CMAX; i += 256) {
        if (i < cnt) {
            float s = 0.0f;
#pragma unroll
            for (int hq = 0; hq < 4; hq++)
                s += g_cpart[((size_t)hq * B_ + b) * CMAX + i];
            cs[i] = s; cid[i] = g_cand[b * CMAX + i];
        } else { cs[i] = -FLT_MAX; cid[i] = 0x7fffffff; }
    }
    __syncthreads();

    for (int i = t; i < CMAX; i += 256) {
        const float si = cs[i];
        const int idi = cid[i];
        if (idi == 0x7fffffff) continue;
        int rank = 0;
#pragma unroll 8
        for (int j = 0; j < CMAX; j++) {
            const float sj = cs[j];
            rank += (sj > si) || (sj == si && cid[j] < idi);
        }
        if (rank < KSEL) g_topk[b * KSEL + rank] = idi;
    }
}

// =====================================================================
// Kernel 5: projection, 2-stage cp.async pipeline, 2 CTAs/SM, 3-mma split
// grid (32 o-tiles, 25 row-tiles), 256 thr, 80KB dynamic smem
// =====================================================================
__global__ void __launch_bounds__(256, 2)
proj_kernel(const float* __restrict__ bp, float* __restrict__ out) {
    extern __shared__ __align__(16) unsigned char dsm[];   // [2][4][TILESZ]

    const int t = threadIdx.x, lane = t & 31, w = t >> 5;
    const int wm = w & 1, wn = w >> 1;
    const int o0 = blockIdx.x * 128, r0 = blockIdx.y * 128;
    const int lrow = t >> 1;

    const __half* Ahg = g_xhi  + (size_t)(r0 + lrow) * D_ + (t & 1) * 16;
    const __half* Alg = g_xlo  + (size_t)(r0 + lrow) * D_ + (t & 1) * 16;
    const __half* Bhg = g_wphi + (size_t)(o0 + lrow) * D_ + (t & 1) * 16;
    const __half* Blg = g_wplo + (size_t)(o0 + lrow) * D_ + (t & 1) * 16;
    const uint32_t smb   = smem_u32(dsm);
    const uint32_t stoff = (uint32_t)lrow * TSTRIDE + (t & 1) * 32;

    auto issue = [&](int c, int s) {
        const uint32_t d = smb + (uint32_t)s * 4 * TILESZ + stoff;
        cpa16(d,                   Ahg + c * 32);
        cpa16(d + 16,              Ahg + c * 32 + 8);
        cpa16(d + TILESZ,          Alg + c * 32);
        cpa16(d + TILESZ + 16,     Alg + c * 32 + 8);
        cpa16(d + 2 * TILESZ,      Bhg + c * 32);
        cpa16(d + 2 * TILESZ + 16, Bhg + c * 32 + 8);
        cpa16(d + 3 * TILESZ,      Blg + c * 32);
        cpa16(d + 3 * TILESZ + 16, Blg + c * 32 + 8);
    };
    issue(0, 0); CP_COMMIT();
    issue(1, 1); CP_COMMIT();

    float c[4][4][4];
#pragma unroll
    for (int mi = 0; mi < 4; mi++)
#pragma unroll
        for (int nj = 0; nj < 4; nj++)
#pragma unroll
            for (int e = 0; e < 4; e++) c[mi][nj][e] = 0.0f;

    for (int j = 0; j < 32; j++) {
        CP_WAIT1();
        __syncthreads();
        const int slot = j & 1;
        const uint32_t Ahi = smb + (uint32_t)slot * 4 * TILESZ;
        const uint32_t Alo = Ahi + TILESZ;
        const uint32_t Bhi = Ahi + 2 * TILESZ;
        const uint32_t Blo = Ahi + 3 * TILESZ;
        const uint32_t aoff = (uint32_t)(64 * wm + (lane & 7) + 8 * ((lane >> 3) & 1)) * TSTRIDE + (uint32_t)(8 * (lane >> 4)) * 2;
        const uint32_t boff = (uint32_t)(32 * wn + (lane & 7) + 8 * (lane >> 4)) * TSTRIDE + (uint32_t)(8 * ((lane >> 3) & 1)) * 2;
#pragma unroll
        for (int ks = 0; ks < 2; ks++) {
            const uint32_t kb = (uint32_t)(ks * 16) * 2;
            uint32_t Ah[4][4], Al[4][4], Bh[2][4], Bl[2][4];
#pragma unroll
            for (int mi = 0; mi < 4; mi++) {
                ldsm4(Ah[mi], Ahi + aoff + (uint32_t)(16 * mi) * TSTRIDE + kb);
                ldsm4(Al[mi], Alo + aoff + (uint32_t)(16 * mi) * TSTRIDE + kb);
            }
#pragma unroll
            for (int np = 0; np < 2; np++) {
                ldsm4(Bh[np], Bhi + boff + (uint32_t)(16 * np) * TSTRIDE + kb);
                ldsm4(Bl[np], Blo + boff + (uint32_t)(16 * np) * TSTRIDE + kb);
            }
#pragma unroll
            for (int mi = 0; mi < 4; mi++)
#pragma unroll
                for (int nj = 0; nj < 4; nj++) {
                    mma16816(c[mi][nj], Ah[mi], &Bh[nj >> 1][(nj & 1) * 2]);
                    mma16816(c[mi][nj], Ah[mi], &Bl[nj >> 1][(nj & 1) * 2]);
                    mma16816(c[mi][nj], Al[mi], &Bh[nj >> 1][(nj & 1) * 2]);
                }
        }
        __syncthreads();   // all warps done reading this slot before overwrite
        if (j + 2 < 32) issue(j + 2, slot);
        CP_COMMIT();
    }

#pragma unroll
    for (int mi = 0; mi < 4; mi++)
#pragma unroll
        for (int nj = 0; nj < 4; nj++)
#pragma unroll
            for (int rh = 0; rh < 2; rh++) {
                const int R  = r0 + 64 * wm + 16 * mi + (lane >> 2) + 8 * rh;
                const int oc = o0 + 32 * wn + 8 * nj + 2 * (lane & 3);
                float2 v;
                v.x = c[mi][nj][2 * rh + 0] + __ldg(&bp[oc]);
                v.y = c[mi][nj][2 * rh + 1] + __ldg(&bp[oc + 1]);
                *(float2*)(out + (size_t)R * O_ + oc) = v;
            }
}

// =====================================================================
// Entry point
// =====================================================================
extern "C" void kernel_launch(void* const* d_in, const int* in_sizes, int n_in,
                              void* d_out, int out_size) {
    (void)in_sizes; (void)n_in; (void)out_size;
    const float* x  = (const float*)d_in[0];
    const float* W1 = (const float*)d_in[1];
    const float* b1 = (const float*)d_in[2];
    const float* W2 = (const float*)d_in[3];
    // d_in[4] = b2: constant shift, irrelevant to topk ordering
    const float* Wp = (const float*)d_in[5];
    const float* bp = (const float*)d_in[6];
    float* out = (float*)d_out;

    cudaFuncSetAttribute(approx_score_kernel, cudaFuncAttributeMaxDynamicSharedMemorySize, APPROX_SMEM);
    cudaFuncSetAttribute(proj_kernel,         cudaFuncAttributeMaxDynamicSharedMemorySize, PROJ_SMEM);

    conv_w_kernel<<<H_ + O_, 256>>>(W1, Wp);
    approx_score_kernel<<<dim3(4, TOK / 128), 256, APPROX_SMEM>>>(x, b1, W2);
    radix_cand_kernel<<<B_, 1024>>>();
    exact_score_kernel<<<dim3(CT64, 16, B_), 256>>>(x, W1);
    exact_combine_kernel<<<dim3(B_, 4), 256>>>(b1, W2);
    final_topk_kernel<<<B_, 256>>>();
    gather_conv_kernel<<<RTOT, 256>>>(x);
    proj_kernel<<<dim3(O_ / 128, RTOT / 128), 256, PROJ_SMEM>>>(bp, out);
}

// round 17
// speedup vs baseline: 1.2673x; 1.2286x over previous
#include <cuda_runtime.h>
#include <cuda_fp16.h>
#include <cfloat>
#include <cstdint>

#define B_   16
#define N_   4096
#define D_   1024
#define H_   512
#define O_   4096
#define KSEL 200
#define TOK  (B_ * N_)        // 65536
#define RTOT (B_ * KSEL)      // 3200 output rows
#define CMAX 320
#define RSEL 256              // radix threshold rank
#define CT64 5                // CMAX/64 tiles for exact rescore
#define NPART 16              // exact raw partials: 4 hq x 4 kquarter

// Scratch globals (no cudaMalloc allowed)
__device__ float  g_part[4 * TOK];            // approx score partials per h-quarter
__device__ int    g_cand[B_ * CMAX];
__device__ int    g_ccount[B_];
__device__ float  g_cpart[4 * B_ * CMAX];     // exact per-hq score partials
__device__ int    g_topk[B_ * KSEL];
__device__ float  g_cdot[(size_t)NPART * B_ * CMAX * 128];  // raw dot partials
__device__ __half g_w1h[H_ * D_];             // W1 in fp16 (approx stage)
__device__ __half g_wph[O_ * D_];             // Wp fp16
__device__ __half g_xg[RTOT * D_];            // gathered selected rows fp16

// ---------------- helpers ----------------
__device__ __forceinline__ uint32_t smem_u32(const void* p) {
    uint32_t a;
    asm("{ .reg .u64 t; cvta.to.shared.u64 t, %1; cvt.u32.u64 %0, t; }" : "=r"(a) : "l"(p));
    return a;
}
__device__ __forceinline__ float gelu_exact(float v) {
    return 0.5f * v * (1.0f + erff(v * 0.70710678118654752440f));
}
// fast gelu: only used for candidate SELECTION (rank margin 56 >> err)
__device__ __forceinline__ float gelu_fast(float v) {
    return __fdividef(v, 1.0f + __expf(-1.702f * v));
}
__device__ __forceinline__ void ldsm4(uint32_t* r, uint32_t addr) {
    asm volatile("ldmatrix.sync.aligned.m8n8.x4.shared.b16 {%0,%1,%2,%3}, [%4];"
                 : "=r"(r[0]), "=r"(r[1]), "=r"(r[2]), "=r"(r[3]) : "r"(addr));
}
__device__ __forceinline__ void mma16816(float* c, const uint32_t* a, const uint32_t* b) {
    asm volatile("mma.sync.aligned.m16n8k16.row.col.f32.f16.f16.f32 "
                 "{%0,%1,%2,%3}, {%4,%5,%6,%7}, {%8,%9}, {%0,%1,%2,%3};"
                 : "+f"(c[0]), "+f"(c[1]), "+f"(c[2]), "+f"(c[3])
                 : "r"(a[0]), "r"(a[1]), "r"(a[2]), "r"(a[3]), "r"(b[0]), "r"(b[1]));
}
__device__ __forceinline__ void cpa16(uint32_t dst, const void* src) {
    asm volatile("cp.async.cg.shared.global [%0], [%1], 16;" :: "r"(dst), "l"(src));
}
#define CP_COMMIT() asm volatile("cp.async.commit_group;" ::: "memory")
#define CP_WAIT1()  asm volatile("cp.async.wait_group 1;" ::: "memory")
#define CP_WAIT2()  asm volatile("cp.async.wait_group 2;" ::: "memory")
// f32x2 packed FMA helpers
__device__ __forceinline__ unsigned long long pack2(float lo, float hi) {
    unsigned long long r;
    asm("mov.b64 %0, {%1, %2};" : "=l"(r) : "f"(lo), "f"(hi));
    return r;
}
__device__ __forceinline__ void unpack2(unsigned long long v, float& lo, float& hi) {
    asm("mov.b64 {%0, %1}, %2;" : "=f"(lo), "=f"(hi) : "l"(v));
}
__device__ __forceinline__ void fma2(unsigned long long& c, unsigned long long a,
                                     unsigned long long b) {
    asm("fma.rn.f32x2 %0, %1, %2, %0;" : "+l"(c) : "l"(a), "l"(b));
}

#define TSTRIDE 80                // 64B data + 16B pad (conflict-free ldmatrix)
#define TILESZ  (128 * TSTRIDE)   // 10240 bytes
#define APPROX_SMEM (4 * 2 * TILESZ + 2048)   // 4 stages x (A+B) + red
#define PROJ_SMEM   (2 * 2 * TILESZ)          // 2 stages x (A,B) = 40KB

// =====================================================================
// Convert kernel: W1->fp16, Wp->fp16 (x converted inline in approx)
// =====================================================================
__global__ void __launch_bounds__(256)
conv_w_kernel(const float* __restrict__ W1, const float* __restrict__ Wp) {
    const int bid = blockIdx.x, t = threadIdx.x;
    if (bid < H_) {
        const size_t base = (size_t)bid * D_ + 4 * t;
        const float4 v = *(const float4*)(W1 + base);
        const __half2 h0 = __floats2half2_rn(v.x, v.y), h1 = __floats2half2_rn(v.z, v.w);
        *(uint2*)&g_w1h[base] = make_uint2(*(const uint32_t*)&h0, *(const uint32_t*)&h1);
    } else {
        const size_t base = (size_t)(bid - H_) * D_ + 4 * t;
        const float4 v = *(const float4*)(Wp + base);
        const __half2 h0 = __floats2half2_rn(v.x, v.y), h1 = __floats2half2_rn(v.z, v.w);
        *(uint2*)&g_wph[base] = make_uint2(*(const uint32_t*)&h0, *(const uint32_t*)&h1);
    }
}

__global__ void __launch_bounds__(256)
gather_conv_kernel(const float* __restrict__ x) {
    const int r = blockIdx.x, t = threadIdx.x;
    const int b = r / KSEL;
    const int tok = g_topk[r];
    const float4 v = *(const float4*)(x + ((size_t)b * N_ + tok) * D_ + 4 * t);
    const __half2 h0 = __floats2half2_rn(v.x, v.y), h1 = __floats2half2_rn(v.z, v.w);
    *(uint2*)&g_xg[(size_t)r * D_ + 4 * t] = make_uint2(*(const uint32_t*)&h0, *(const uint32_t*)&h1);
}

// =====================================================================
// Kernel 1: approx scores via fp16 HMMA  (R13-measured version)
// A: fp32 LDG + inline cvt + STS (register double-buffer)
// B: 4-stage cp.async from precomputed g_w1h
// grid (4 hq, 512 m-tiles), 256 thr
// =====================================================================
__global__ void __launch_bounds__(256)
approx_score_kernel(const float* __restrict__ x,
                    const float* __restrict__ b1, const float* __restrict__ W2) {
    extern __shared__ __align__(16) unsigned char dsm[];
    float* red = (float*)(dsm + 4 * 2 * TILESZ);   // [128][4]

    const int t = threadIdx.x, lane = t & 31, w = t >> 5;
    const int hq = blockIdx.x, m0 = blockIdx.y * 128;
    const int wm = w & 1, wn = w >> 1;
    const int lrow = t >> 1;
    const float*  Axf  = x + (size_t)(m0 + lrow) * D_ + (t & 1) * 16;
    const __half* Bsrc = g_w1h + (size_t)(hq * 128 + lrow) * D_ + (t & 1) * 16;
    const uint32_t smb   = smem_u32(dsm);
    const uint32_t stoff = (uint32_t)lrow * TSTRIDE + (t & 1) * 32;

    float4 av[4];
    auto ldA = [&](int c) {
#pragma unroll
        for (int q = 0; q < 4; q++) av[q] = *(const float4*)(Axf + c * 32 + 4 * q);
    };
    auto stA = [&](int s) {
        uint32_t h[8];
#pragma unroll
        for (int q = 0; q < 4; q++) {
            const __half2 p0 = __floats2half2_rn(av[q].x, av[q].y);
            const __half2 p1 = __floats2half2_rn(av[q].z, av[q].w);
            h[2 * q]     = *(const uint32_t*)&p0;
            h[2 * q + 1] = *(const uint32_t*)&p1;
        }
        unsigned char* d = dsm + (size_t)s * 2 * TILESZ + stoff;
        *(uint4*)(d)      = make_uint4(h[0], h[1], h[2], h[3]);
        *(uint4*)(d + 16) = make_uint4(h[4], h[5], h[6], h[7]);
    };
    auto issueB = [&](int c, int s) {
        const uint32_t d = smb + (uint32_t)s * 2 * TILESZ + TILESZ + stoff;
        cpa16(d,      Bsrc + c * 32);
        cpa16(d + 16, Bsrc + c * 32 + 8);
    };

    // prologue
    ldA(0);
    issueB(0, 0); CP_COMMIT();
    issueB(1, 1); CP_COMMIT();
    issueB(2, 2); CP_COMMIT();
    stA(0);
    ldA(1);

    float c[4][4][4];
#pragma unroll
    for (int mi = 0; mi < 4; mi++)
#pragma unroll
        for (int nj = 0; nj < 4; nj++)
#pragma unroll
            for (int e = 0; e < 4; e++) c[mi][nj][e] = 0.0f;

    for (int j = 0; j < 32; j++) {
        CP_WAIT2();
        __syncthreads();
        const int slot = j & 3;
        const uint32_t Abase = smb + (uint32_t)slot * 2 * TILESZ;
        const uint32_t Bbase = Abase + TILESZ;
#pragma unroll
        for (int ks = 0; ks < 2; ks++) {
            const int k0h = ks * 16;
            uint32_t Af[4][4], Bf[2][4];
#pragma unroll
            for (int mi = 0; mi < 4; mi++)
                ldsm4(Af[mi], Abase + (uint32_t)(64 * wm + 16 * mi + (lane & 7) + 8 * ((lane >> 3) & 1)) * TSTRIDE
                              + (uint32_t)(k0h + 8 * (lane >> 4)) * 2);
#pragma unroll
            for (int np = 0; np < 2; np++)
                ldsm4(Bf[np], Bbase + (uint32_t)(32 * wn + 16 * np + (lane & 7) + 8 * (lane >> 4)) * TSTRIDE
                              + (uint32_t)(k0h + 8 * ((lane >> 3) & 1)) * 2);
#pragma unroll
            for (int mi = 0; mi < 4; mi++)
#pragma unroll
                for (int nj = 0; nj < 4; nj++)
                    mma16816(c[mi][nj], Af[mi], &Bf[nj >> 1][(nj & 1) * 2]);
        }
        if (j + 1 < 32) stA((j + 1) & 3);   // store prefetched A chunk j+1
        if (j + 2 < 32) ldA(j + 2);          // prefetch A chunk j+2
        if (j + 3 < 32) issueB(j + 3, (j + 3) & 3);
        CP_COMMIT();
    }

    // epilogue: +b1, fast-gelu, .W2 -> per-row partial
    float pr[4][2];
#pragma unroll
    for (int mi = 0; mi < 4; mi++) { pr[mi][0] = 0.0f; pr[mi][1] = 0.0f; }
#pragma unroll
    for (int mi = 0; mi < 4; mi++)
#pragma unroll
        for (int nj = 0; nj < 4; nj++)
#pragma unroll
            for (int e = 0; e < 4; e++) {
                const int h = hq * 128 + 32 * wn + 8 * nj + 2 * (lane & 3) + (e & 1);
                const float v = c[mi][nj][e] + __ldg(&b1[h]);
                pr[mi][e >> 1] += gelu_fast(v) * __ldg(&W2[h]);
            }
    __syncthreads();
#pragma unroll
    for (int mi = 0; mi < 4; mi++)
#pragma unroll
        for (int rh = 0; rh < 2; rh++) {
            float p = pr[mi][rh];
            p += __shfl_xor_sync(0xffffffffu, p, 1);
            p += __shfl_xor_sync(0xffffffffu, p, 2);
            if ((lane & 3) == 0) red[(64 * wm + 16 * mi + (lane >> 2) + 8 * rh) * 4 + wn] = p;
        }
    __syncthreads();
    if (t < 128)
        g_part[hq * TOK + m0 + t] = red[t * 4 + 0] + red[t * 4 + 1] + red[t * 4 + 2] + red[t * 4 + 3];
}

// =====================================================================
// Kernel 2: per-batch radix-select threshold at rank RSEL (1024 threads)
// =====================================================================
__global__ void __launch_bounds__(1024)
radix_cand_kernel() {
    __shared__ uint32_t key[N_];
    __shared__ int hist[256];
    __shared__ uint32_t s_prefix;
    __shared__ int s_remaining, s_cnt;
    const int b = blockIdx.x, t = threadIdx.x;

    for (int i = t; i < N_; i += 1024) {
        const int g = b * N_ + i;
        const float s = g_part[g] + g_part[TOK + g] + g_part[2 * TOK + g] + g_part[3 * TOK + g];
        const uint32_t u = __float_as_uint(s);
        key[i] = (u & 0x80000000u) ? ~u : (u | 0x80000000u);
    }
    if (t == 0) { s_prefix = 0; s_remaining = RSEL; s_cnt = 0; }
    __syncthreads();

    for (int pass = 0; pass < 3; pass++) {
        const int shift = 24 - pass * 8;
        if (t < 256) hist[t] = 0;
        __syncthreads();
        const uint32_t pref = s_prefix;
        for (int i = t; i < N_; i += 1024) {
            const uint32_t k = key[i];
            const bool match = (pass == 0) || ((k >> (shift + 8)) == pref);
            if (match) atomicAdd(&hist[(k >> shift) & 255], 1);
        }
        __syncthreads();
        if (t == 0) {
            int rem = s_remaining, acc = 0, v = 255;
            for (; v > 0; v--) { if (acc + hist[v] >= rem) break; acc += hist[v]; }
            s_prefix = (pref << 8) | (uint32_t)v;
            s_remaining = rem - acc;
        }
        __syncthreads();
    }

    const uint32_t thr = s_prefix;
    for (int i = t; i < N_; i += 1024) {
        if ((key[i] >> 8) >= thr) {
            const int pos = atomicAdd(&s_cnt, 1);
            if (pos < CMAX) g_cand[b * CMAX + pos] = i;
        }
    }
    __syncthreads();
    const int cnt = min(s_cnt, CMAX);
    if (t == 0) g_ccount[b] = cnt;
    for (int i = cnt + t; i < CMAX; i += 1024) g_cand[b * CMAX + i] = 0;
}

// =====================================================================
// Kernel 3: exact fp32 rescoring, 64 cand x 128 h x 256 k per CTA
// grid (CT64, 16, B_): blockIdx.y = hq*4 + kquarter -> 1280 CTAs, 3/SM
// thread = 4 cand x 8 h; Bs[k][h-chunk padded to 10] -> conflict-free
// =====================================================================
#define ASTR 36    // As row stride (32 data + 4 pad, 144B 16B-aligned)
#define BSTR 160   // Bs row stride in floats (16 chunks x 10)
__global__ void __launch_bounds__(256, 3)
exact_score_kernel(const float* __restrict__ x, const float* __restrict__ W1) {
    const int ct = blockIdx.x, yb = blockIdx.y, b = blockIdx.z;
    const int hq = yb >> 2, kq = yb & 3;
    if (ct * 64 >= g_ccount[b]) return;

    __shared__ __align__(16) float As[64][ASTR];   // [cand][k]
    __shared__ __align__(16) float Bs[32][BSTR];   // [k][h-chunk*10]
    __shared__ int cidx[64];
    const int t = threadIdx.x;
    if (t < 64) cidx[t] = g_cand[b * CMAX + ct * 64 + t];
    __syncthreads();

    const int cg = t >> 4;        // 0..15 candidate group (4 cand each)
    const int hg = t & 15;        // 0..15 h group (8 h each)
    const int cb = cg * 4;

    // loaders
    const int arow = t >> 2, acol = (t & 3) * 8;
    const int bh   = t >> 1, bks = (t & 1) * 16;
    const float* Agr = x  + ((size_t)b * N_ + cidx[arow]) * D_ + kq * 256 + acol;
    const float* Bgr = W1 + (size_t)(hq * 128 + bh) * D_ + kq * 256 + bks;
    const int bchunk = bh >> 3, blane = bh & 7;

    unsigned long long acc[4][4];   // [cand][h-pair]
#pragma unroll
    for (int ci = 0; ci < 4; ci++)
#pragma unroll
        for (int j = 0; j < 4; j++) acc[ci][j] = pack2(0.0f, 0.0f);

    for (int k0 = 0; k0 < 256; k0 += 32) {
        const float4 a0 = *(const float4*)(Agr + k0);
        const float4 a1 = *(const float4*)(Agr + k0 + 4);
        float4 bw[4];
#pragma unroll
        for (int q = 0; q < 4; q++) bw[q] = *(const float4*)(Bgr + k0 + 4 * q);
        __syncthreads();
        *(float4*)&As[arow][acol]     = a0;
        *(float4*)&As[arow][acol + 4] = a1;
#pragma unroll
        for (int q = 0; q < 4; q++) {
            Bs[bks + 4 * q + 0][bchunk * 10 + blane] = bw[q].x;
            Bs[bks + 4 * q + 1][bchunk * 10 + blane] = bw[q].y;
            Bs[bks + 4 * q + 2][bchunk * 10 + blane] = bw[q].z;
            Bs[bks + 4 * q + 3][bchunk * 10 + blane] = bw[q].w;
        }
        __syncthreads();
#pragma unroll
        for (int kk = 0; kk < 32; kk++) {
            const unsigned long long* brow = (const unsigned long long*)&Bs[kk][hg * 10];
            const unsigned long long b0 = brow[0], b1v = brow[1], b2 = brow[2], b3 = brow[3];
#pragma unroll
            for (int ci = 0; ci < 4; ci++) {
                const float avv = As[cb + ci][kk];
                const unsigned long long aa = pack2(avv, avv);
                fma2(acc[ci][0], aa, b0); fma2(acc[ci][1], aa, b1v);
                fma2(acc[ci][2], aa, b2); fma2(acc[ci][3], aa, b3);
            }
        }
    }

    // write raw 8-h dot partials per thread to g_cdot (combine applies gelu)
#pragma unroll
    for (int ci = 0; ci < 4; ci++) {
#pragma unroll
        for (int j = 0; j < 4; j++) {
            float c0, c1;
            unpack2(acc[ci][j], c0, c1);
            const size_t base = ((((size_t)yb * B_ + b) * CMAX) + ct * 64 + cb + ci) * 128
                                + hg * 8 + 2 * j;
            g_cdot[base]     = c0;
            g_cdot[base + 1] = c1;
        }
    }
}

// =====================================================================
// Kernel 3b: combine k-quarters, apply exact gelu.W2 -> per-hq partials
// grid (B_, 4): CTA = (batch, h-quarter); 64 CTAs total
// =====================================================================
__global__ void __launch_bounds__(256)
exact_combine_kernel(const float* __restrict__ b1, const float* __restrict__ W2) {
    __shared__ float sb1[128], sw2[128];
    const int b = blockIdx.x, hq = blockIdx.y, t = threadIdx.x;
    if (t < 128) { sb1[t] = b1[hq * 128 + t]; sw2[t] = W2[hq * 128 + t]; }
    __syncthreads();
    const int cnt = g_ccount[b];
    for (int i = t; i < cnt; i += 256) {
        const size_t p0 = ((((size_t)(hq * 4 + 0) * B_ + b) * CMAX) + i) * 128;
        const size_t p1 = ((((size_t)(hq * 4 + 1) * B_ + b) * CMAX) + i) * 128;
        const size_t p2 = ((((size_t)(hq * 4 + 2) * B_ + b) * CMAX) + i) * 128;
        const size_t p3 = ((((size_t)(hq * 4 + 3) * B_ + b) * CMAX) + i) * 128;
        float s = 0.0f;
        for (int hh = 0; hh < 128; hh += 4) {
            const float4 d0 = *(const float4*)&g_cdot[p0 + hh];
            const float4 d1 = *(const float4*)&g_cdot[p1 + hh];
            const float4 d2 = *(const float4*)&g_cdot[p2 + hh];
            const float4 d3 = *(const float4*)&g_cdot[p3 + hh];
            s += gelu_exact(d0.x + d1.x + d2.x + d3.x + sb1[hh])     * sw2[hh];
            s += gelu_exact(d0.y + d1.y + d2.y + d3.y + sb1[hh + 1]) * sw2[hh + 1];
            s += gelu_exact(d0.z + d1.z + d2.z + d3.z + sb1[hh + 2]) * sw2[hh + 2];
            s += gelu_exact(d0.w + d1.w + d2.w + d3.w + sb1[hh + 3]) * sw2[hh + 3];
        }
        g_cpart[((size_t)hq * B_ + b) * CMAX + i] = s;
    }
}

// =====================================================================
// Kernel 4: rank-by-counting final top-200 (fully parallel, deterministic)
// =====================================================================
__global__ void __launch_bounds__(256)
final_topk_kernel() {
    __shared__ float cs[CMAX];
    __shared__ int   cid[CMAX];
    const int b = blockIdx.x, t = threadIdx.x;
    const int cnt = g_ccount[b];

    for (int i = t; i < CMAX; i += 256) {
        if (i < cnt) {
            float s = 0.0f;
#pragma unroll
            for (int hq = 0; hq < 4; hq++)
                s += g_cpart[((size_t)hq * B_ + b) * CMAX + i];
            cs[i] = s; cid[i] = g_cand[b * CMAX + i];
        } else { cs[i] = -FLT_MAX; cid[i] = 0x7fffffff; }
    }
    __syncthreads();

    for (int i = t; i < CMAX; i += 256) {
        const float si = cs[i];
        const int idi = cid[i];
        if (idi == 0x7fffffff) continue;
        int rank = 0;
#pragma unroll 8
        for (int j = 0; j < CMAX; j++) {
            const float sj = cs[j];
            rank += (sj > si) || (sj == si && cid[j] < idi);
        }
        if (rank < KSEL) g_topk[b * KSEL + rank] = idi;
    }
}

// =====================================================================
// Kernel 5: projection, single fp16 mma (error ~4e-4 << 1e-3 tolerance)
// 2-stage cp.async pipeline, grid (32 o-tiles, 25 row-tiles), 40KB smem
// =====================================================================
__global__ void __launch_bounds__(256, 2)
proj_kernel(const float* __restrict__ bp, float* __restrict__ out) {
    extern __shared__ __align__(16) unsigned char dsm[];   // [2][2][TILESZ]: A,B

    const int t = threadIdx.x, lane = t & 31, w = t >> 5;
    const int wm = w & 1, wn = w >> 1;
    const int o0 = blockIdx.x * 128, r0 = blockIdx.y * 128;
    const int lrow = t >> 1;

    const __half* Ag = g_xg  + (size_t)(r0 + lrow) * D_ + (t & 1) * 16;
    const __half* Bg = g_wph + (size_t)(o0 + lrow) * D_ + (t & 1) * 16;
    const uint32_t smb   = smem_u32(dsm);
    const uint32_t stoff = (uint32_t)lrow * TSTRIDE + (t & 1) * 32;

    auto issue = [&](int c, int s) {
        const uint32_t d = smb + (uint32_t)s * 2 * TILESZ + stoff;
        cpa16(d,               Ag + c * 32);
        cpa16(d + 16,          Ag + c * 32 + 8);
        cpa16(d + TILESZ,      Bg + c * 32);
        cpa16(d + TILESZ + 16, Bg + c * 32 + 8);
    };
    issue(0, 0); CP_COMMIT();
    issue(1, 1); CP_COMMIT();

    float c[4][4][4];
#pragma unroll
    for (int mi = 0; mi < 4; mi++)
#pragma unroll
        for (int nj = 0; nj < 4; nj++)
#pragma unroll
            for (int e = 0; e < 4; e++) c[mi][nj][e] = 0.0f;

    for (int j = 0; j < 32; j++) {
        CP_WAIT1();
        __syncthreads();
        const int slot = j & 1;
        const uint32_t Abase = smb + (uint32_t)slot * 2 * TILESZ;
        const uint32_t Bbase = Abase + TILESZ;
#pragma unroll
        for (int ks = 0; ks < 2; ks++) {
            const int k0h = ks * 16;
            uint32_t Af[4][4], Bf[2][4];
#pragma unroll
            for (int mi = 0; mi < 4; mi++)
                ldsm4(Af[mi], Abase + (uint32_t)(64 * wm + 16 * mi + (lane & 7) + 8 * ((lane >> 3) & 1)) * TSTRIDE
                              + (uint32_t)(k0h + 8 * (lane >> 4)) * 2);
#pragma unroll
            for (int np = 0; np < 2; np++)
                ldsm4(Bf[np], Bbase + (uint32_t)(32 * wn + 16 * np + (lane & 7) + 8 * (lane >> 4)) * TSTRIDE
                              + (uint32_t)(k0h + 8 * ((lane >> 3) & 1)) * 2);
#pragma unroll
            for (int mi = 0; mi < 4; mi++)
#pragma unroll
                for (int nj = 0; nj < 4; nj++)
                    mma16816(c[mi][nj], Af[mi], &Bf[nj >> 1][(nj & 1) * 2]);
        }
        __syncthreads();   // all warps done reading this slot before overwrite
        if (j + 2 < 32) issue(j + 2, slot);
        CP_COMMIT();
    }

#pragma unroll
    for (int mi = 0; mi < 4; mi++)
#pragma unroll
        for (int nj = 0; nj < 4; nj++)
#pragma unroll
            for (int rh = 0; rh < 2; rh++) {
                const int R  = r0 + 64 * wm + 16 * mi + (lane >> 2) + 8 * rh;
                const int oc = o0 + 32 * wn + 8 * nj + 2 * (lane & 3);
                float2 v;
                v.x = c[mi][nj][2 * rh + 0] + __ldg(&bp[oc]);
                v.y = c[mi][nj][2 * rh + 1] + __ldg(&bp[oc + 1]);
                *(float2*)(out + (size_t)R * O_ + oc) = v;
            }
}

// =====================================================================
// Entry point
// =====================================================================
extern "C" void kernel_launch(void* const* d_in, const int* in_sizes, int n_in,
                              void* d_out, int out_size) {
    (void)in_sizes; (void)n_in; (void)out_size;
    const float* x  = (const float*)d_in[0];
    const float* W1 = (const float*)d_in[1];
    const float* b1 = (const float*)d_in[2];
    const float* W2 = (const float*)d_in[3];
    // d_in[4] = b2: constant shift, irrelevant to topk ordering
    const float* Wp = (const float*)d_in[5];
    const float* bp = (const float*)d_in[6];
    float* out = (float*)d_out;

    cudaFuncSetAttribute(approx_score_kernel, cudaFuncAttributeMaxDynamicSharedMemorySize, APPROX_SMEM);
    cudaFuncSetAttribute(proj_kernel,         cudaFuncAttributeMaxDynamicSharedMemorySize, PROJ_SMEM);

    conv_w_kernel<<<H_ + O_, 256>>>(W1, Wp);
    approx_score_kernel<<<dim3(4, TOK / 128), 256, APPROX_SMEM>>>(x, b1, W2);
    radix_cand_kernel<<<B_, 1024>>>();
    exact_score_kernel<<<dim3(CT64, 16, B_), 256>>>(x, W1);
    exact_combine_kernel<<<dim3(B_, 4), 256>>>(b1, W2);
    final_topk_kernel<<<B_, 256>>>();
    gather_conv_kernel<<<RTOT, 256>>>(x);
    proj_kernel<<<dim3(O_ / 128, RTOT / 128), 256, PROJ_SMEM>>>(bp, out);
}